// round 10
// baseline (speedup 1.0000x reference)
#include <cuda_runtime.h>
#include <cuda_fp16.h>
#include <math.h>
#include <stdint.h>

// Model constants
#define BB 4
#define TT 1024
#define DD 1024
#define HH 16
#define HS 64
#define LL 8
#define FFD 4096
#define VV 32000
#define NTOK (BB*TT)          // 4096
#define NQKV 3072
#define ATT_SCALE 0.03125f    // D^-0.5 = 1/32

// fp16 GEMM tile config: 128x256x32, 512 threads, 3-stage cp.async ring
#define BM 128
#define BN 256
#define BK 32                 // halfs per k-slab
#define STG 3
#define A_STRIDE 40           // halfs per A smem row (pad 32->40)
#define B_STRIDE 40
#define A_SLAB_B (BM*A_STRIDE*2)     // 10240 B
#define B_SLAB_B (BN*B_STRIDE*2)     // 20480 B
#define SLAB_B (A_SLAB_B + B_SLAB_B) // 30720 B
#define GEMM_SMEM (STG*SLAB_B)       // 92160 B
#define GEMM_THREADS 512

// Weight scratch offsets (transposed [N][K] half copies)
#define SQ  (LL*HH*DD*HS)        // 8388608
#define SO  (LL*DD*DD)           // 8388608
#define S1  (LL*DD*FFD)          // 33554432
#define SLM (DD*VV)              // 32768000
#define OFF_QKV 0                // [L][3072][1024]
#define OFF_O  (3*SQ)            // [L][1024][1024]
#define OFF_W1 (3*SQ + SO)       // [L][4096][1024]
#define OFF_W2 (3*SQ + SO + S1)  // [L][1024][4096]
#define OFF_LM (3*SQ + SO + 2*S1)// [32000][1024]
#define WTOT   (3*SQ + SO + 2*S1 + SLM)

// transpose tile counts
#define NT_QKV (3*LL*HH*64)      // 24576
#define NT_WO  (LL*32*32)        // 8192
#define NT_W1  (LL*32*128)       // 32768
#define NT_W2  (LL*128*32)       // 32768
#define NT_LM  (32*1000)         // 32000
#define NT_ALL (NT_QKV+NT_WO+NT_W1+NT_W2+NT_LM)  // 130304

// ---------------------------------------------------------------------------
// Scratch (device globals)
// ---------------------------------------------------------------------------
__device__ float  g_x  [(size_t)NTOK*DD];
__device__ __half g_h  [(size_t)NTOK*DD];
__device__ __half g_qkv[(size_t)NTOK*NQKV];
__device__ __half g_att[(size_t)NTOK*DD];
__device__ __half g_ffn[(size_t)NTOK*FFD];
__device__ float  g_rowloss[NTOK];
__device__ __half g_wr [(size_t)WTOT];
__device__ float  g_logits_fb[(size_t)NTOK*VV];

// ---------------------------------------------------------------------------
// Helpers
// ---------------------------------------------------------------------------
__device__ __forceinline__ uint32_t s2u(const void* p) {
    return (uint32_t)__cvta_generic_to_shared(p);
}
__device__ __forceinline__ void cpasync16s(uint32_t saddr, const void* g) {
    asm volatile("cp.async.cg.shared.global [%0], [%1], 16;\n" :: "r"(saddr), "l"(g));
}
__device__ __forceinline__ void cp_commit() { asm volatile("cp.async.commit_group;\n"); }

__device__ __forceinline__ void mma_f16(float c[4], const unsigned a[4], const unsigned b[2]) {
    asm volatile(
        "mma.sync.aligned.m16n8k16.row.col.f32.f16.f16.f32 "
        "{%0,%1,%2,%3}, {%4,%5,%6,%7}, {%8,%9}, {%0,%1,%2,%3};\n"
        : "+f"(c[0]), "+f"(c[1]), "+f"(c[2]), "+f"(c[3])
        : "r"(a[0]), "r"(a[1]), "r"(a[2]), "r"(a[3]), "r"(b[0]), "r"(b[1]));
}

#define LDSM4(r, a) \
    asm volatile("ldmatrix.sync.aligned.m8n8.x4.shared.b16 {%0,%1,%2,%3}, [%4];" \
        : "=r"((r)[0]), "=r"((r)[1]), "=r"((r)[2]), "=r"((r)[3]) : "r"(a))

__device__ __forceinline__ void h8_to_f(uint4 u, float* f) {
    float2 t;
    t = __half22float2(*(const __half2*)&u.x); f[0]=t.x; f[1]=t.y;
    t = __half22float2(*(const __half2*)&u.y); f[2]=t.x; f[3]=t.y;
    t = __half22float2(*(const __half2*)&u.z); f[4]=t.x; f[5]=t.y;
    t = __half22float2(*(const __half2*)&u.w); f[6]=t.x; f[7]=t.y;
}

// ---------------------------------------------------------------------------
// Mega transpose: all weights fp32 [K][N] -> half [N][K] in g_wr, one launch
// ---------------------------------------------------------------------------
__global__ void transpose_all(const float* __restrict__ Wq, const float* __restrict__ Wk,
                              const float* __restrict__ Wv, const float* __restrict__ Wo,
                              const float* __restrict__ W1, const float* __restrict__ W2,
                              const float* __restrict__ lmW, __half* __restrict__ dst) {
    __shared__ float t[32][33];
    int id = blockIdx.x;
    const float* s; __half* d; int sN, dK, kt, nt;

    if (id < NT_QKV) {
        int sel = id / (NT_QKV/3);            // 0=q,1=k,2=v
        int rem = id % (NT_QKV/3);            // 8192
        int mat = rem >> 6;                    // l*16+h
        int tile = rem & 63;
        kt = tile >> 1; nt = tile & 1;
        int l = mat >> 4, h = mat & 15;
        const float* W = sel == 0 ? Wq : (sel == 1 ? Wk : Wv);
        s = W + (size_t)mat * DD * HS;        // [1024][64]
        sN = HS; dK = DD;
        d = dst + OFF_QKV + ((size_t)l*NQKV + sel*DD + h*HS) * DD;
    } else if (id < NT_QKV + NT_WO) {
        int rem = id - NT_QKV;
        int l = rem >> 10; int tile = rem & 1023;
        kt = tile >> 5; nt = tile & 31;
        s = Wo + (size_t)l * DD * DD; sN = DD; dK = DD;
        d = dst + OFF_O + (size_t)l * DD * DD;
    } else if (id < NT_QKV + NT_WO + NT_W1) {
        int rem = id - NT_QKV - NT_WO;
        int l = rem >> 12; int tile = rem & 4095;
        kt = tile >> 7; nt = tile & 127;       // K=1024 (32 kt), N=4096 (128 nt)
        s = W1 + (size_t)l * DD * FFD; sN = FFD; dK = DD;
        d = dst + OFF_W1 + (size_t)l * DD * FFD;
    } else if (id < NT_QKV + NT_WO + NT_W1 + NT_W2) {
        int rem = id - NT_QKV - NT_WO - NT_W1;
        int l = rem >> 12; int tile = rem & 4095;
        kt = tile & 127; nt = tile >> 7;       // K=4096 (128 kt), N=1024 (32 nt)
        s = W2 + (size_t)l * FFD * DD; sN = DD; dK = FFD;
        d = dst + OFF_W2 + (size_t)l * FFD * DD;
    } else {
        int rem = id - NT_QKV - NT_WO - NT_W1 - NT_W2;
        kt = rem % 32; nt = rem / 32;          // K=1024 (32 kt), N=32000 (1000 nt)
        s = lmW; sN = VV; dK = DD;
        d = dst + OFF_LM;
    }

    int tx = threadIdx.x, ty = threadIdx.y;
    #pragma unroll
    for (int i = 0; i < 4; i++) {
        int r = kt*32 + ty + i*8;
        t[ty + i*8][tx] = s[(size_t)r * sN + nt*32 + tx];
    }
    __syncthreads();
    #pragma unroll
    for (int i = 0; i < 4; i++) {
        int n = nt*32 + ty + i*8;
        d[(size_t)n * dK + kt*32 + tx] = __float2half_rn(t[tx][ty + i*8]);
    }
}

// ---------------------------------------------------------------------------
// Embedding (fp32 residual stream)
// ---------------------------------------------------------------------------
__global__ void embed_kernel(const float* __restrict__ tok,
                             const float* __restrict__ pos,
                             const int*   __restrict__ ctx,
                             float* __restrict__ x) {
    int idx = blockIdx.x * blockDim.x + threadIdx.x;
    int col4 = idx & (DD/4 - 1);
    int row  = idx >> 8;
    int t = row & (TT - 1);
    int token = ctx[row];
    float4 a = ((const float4*)(tok + (size_t)token*DD))[col4];
    float4 p = ((const float4*)(pos + (size_t)t*DD))[col4];
    float4 o; o.x=a.x+p.x; o.y=a.y+p.y; o.z=a.z+p.z; o.w=a.w+p.w;
    ((float4*)(x + (size_t)row*DD))[col4] = o;
}

// ---------------------------------------------------------------------------
// LayerNorm: fp32 in, half out (feeds GEMM A)
// ---------------------------------------------------------------------------
__global__ void layernorm_kernel(const float* __restrict__ x,
                                 const float* __restrict__ g,
                                 const float* __restrict__ bta,
                                 __half* __restrict__ out) {
    int row = blockIdx.x, tx = threadIdx.x;
    float4 v = ((const float4*)(x + (size_t)row*DD))[tx];
    float s  = v.x + v.y + v.z + v.w;
    float ss = v.x*v.x + v.y*v.y + v.z*v.z + v.w*v.w;
    __shared__ float sh[16];
    #pragma unroll
    for (int o = 16; o > 0; o >>= 1) {
        s  += __shfl_down_sync(0xffffffffu, s,  o);
        ss += __shfl_down_sync(0xffffffffu, ss, o);
    }
    if ((tx & 31) == 0) { sh[tx>>5] = s; sh[8 + (tx>>5)] = ss; }
    __syncthreads();
    if (tx == 0) {
        float a = 0.f, b2 = 0.f;
        #pragma unroll
        for (int i = 0; i < 8; i++) { a += sh[i]; b2 += sh[8+i]; }
        sh[0] = a; sh[8] = b2;
    }
    __syncthreads();
    float mean = sh[0] * (1.f/DD);
    float var  = sh[8] * (1.f/DD) - mean*mean;
    float r = rsqrtf(var + 1e-5f);
    float4 gg = ((const float4*)g)[tx];
    float4 bb = ((const float4*)bta)[tx];
    __half2 h0 = __floats2half2_rn((v.x-mean)*r*gg.x + bb.x, (v.y-mean)*r*gg.y + bb.y);
    __half2 h1 = __floats2half2_rn((v.z-mean)*r*gg.z + bb.z, (v.w-mean)*r*gg.w + bb.w);
    __half2* op = (__half2*)(out + (size_t)row*DD);
    op[tx*2]   = h0;
    op[tx*2+1] = h1;
}

// ---------------------------------------------------------------------------
// fp16 tensor-core GEMM: C[M,N] = epi(A[M,K] @ Bt[N,K]^T + bias [+Res])
// A row-major [M][K] half, Bt row-major [N][K] half.
// Tile 128x256x32, 512 threads, 16 warps (4Mx4N), 3-stage cp.async,
// single-barrier pipeline, ldmatrix.x4 fragment loads.
// ---------------------------------------------------------------------------
template<bool RELU, bool RES, bool HALF_OUT>
__global__ __launch_bounds__(GEMM_THREADS)
void gemm_h(const __half* __restrict__ A, const __half* __restrict__ Bt,
            const float* __restrict__ bias, const float* __restrict__ Res,
            void* __restrict__ Cv, int M, int N, int K, int ldc) {
    extern __shared__ char sm[];

    int tx = threadIdx.x;
    int lane = tx & 31, w = tx >> 5;
    int gid = lane >> 2, tig = lane & 3;
    int warpM = w & 3;   // 32-row strip
    int warpN = w >> 2;  // 64-col strip
    int bm = blockIdx.y * BM;
    int bn = blockIdx.x * BN;

    float acc[2][8][4];
    #pragma unroll
    for (int mt = 0; mt < 2; mt++)
        #pragma unroll
        for (int nt = 0; nt < 8; nt++)
            #pragma unroll
            for (int i = 0; i < 4; i++) acc[mt][nt][i] = 0.f;

    uint32_t sb = s2u(sm);

    // ldmatrix per-thread offsets (halfs, within slab)
    int lane15 = lane & 15;
    int lhi8 = (lane >> 4) * 8;
    int offA0 = (warpM*32 + lane15) * A_STRIDE + lhi8;          // mt=0
    int offA1 = offA0 + 16 * A_STRIDE;                          // mt=1
    int offB0 = (warpN*64 + lane15) * B_STRIDE + lhi8;          // ntPair 0
    // ntPair p offset = offB0 + p*16*B_STRIDE

    auto load_slab = [&](int st, int k0) {
        uint32_t ab = sb + st * SLAB_B;
        uint32_t bb = ab + A_SLAB_B;
        {
            int r = tx >> 2;
            int c = tx & 3;
            cpasync16s(ab + r * (A_STRIDE*2) + c * 16,
                       A + (size_t)(bm + r) * K + k0 + c * 8);
        }
        #pragma unroll
        for (int i = 0; i < 2; i++) {
            int id = tx + i * GEMM_THREADS;
            int n = id >> 2;
            int c = id & 3;
            cpasync16s(bb + n * (B_STRIDE*2) + c * 16,
                       Bt + (size_t)(bn + n) * K + k0 + c * 8);
        }
    };

    int S = K / BK;
    load_slab(0, 0);    cp_commit();
    load_slab(1, BK);   cp_commit();

    for (int s = 0; s < S; s++) {
        int b = s % STG;
        if (s == S - 1) asm volatile("cp.async.wait_group 0;\n");
        else            asm volatile("cp.async.wait_group 1;\n");
        __syncthreads();

        if (s + 2 < S) {
            load_slab((s + 2) % STG, (s + 2) * BK);
            cp_commit();
        }

        uint32_t abase = sb + b * SLAB_B;
        uint32_t bbase = abase + A_SLAB_B;
        #pragma unroll
        for (int kk = 0; kk < BK; kk += 16) {
            unsigned a0[4], a1[4], bq[4][4];
            LDSM4(a0, abase + (offA0 + kk) * 2);
            LDSM4(a1, abase + (offA1 + kk) * 2);
            #pragma unroll
            for (int p = 0; p < 4; p++)
                LDSM4(bq[p], bbase + (offB0 + p * 16 * B_STRIDE + kk) * 2);
            #pragma unroll
            for (int p = 0; p < 4; p++) {
                unsigned ble[2] = { bq[p][0], bq[p][2] };   // nt = 2p
                unsigned bro[2] = { bq[p][1], bq[p][3] };   // nt = 2p+1
                mma_f16(acc[0][2*p],   a0, ble);
                mma_f16(acc[1][2*p],   a1, ble);
                mma_f16(acc[0][2*p+1], a0, bro);
                mma_f16(acc[1][2*p+1], a1, bro);
            }
        }
    }

    // Epilogue: direct register->gmem
    #pragma unroll
    for (int mt = 0; mt < 2; mt++) {
        int row0 = bm + warpM * 32 + mt * 16 + gid;
        #pragma unroll
        for (int nt = 0; nt < 8; nt++) {
            int col = bn + warpN * 64 + nt * 8 + tig * 2;
            float b0 = 0.f, b1 = 0.f;
            if (bias) { b0 = bias[col]; b1 = bias[col + 1]; }
            float v0 = acc[mt][nt][0] + b0;
            float v1 = acc[mt][nt][1] + b1;
            float v2 = acc[mt][nt][2] + b0;
            float v3 = acc[mt][nt][3] + b1;
            if (RES) {
                v0 += Res[(size_t)row0*ldc + col];
                v1 += Res[(size_t)row0*ldc + col + 1];
                v2 += Res[(size_t)(row0+8)*ldc + col];
                v3 += Res[(size_t)(row0+8)*ldc + col + 1];
            }
            if (RELU) { v0 = fmaxf(v0,0.f); v1 = fmaxf(v1,0.f); v2 = fmaxf(v2,0.f); v3 = fmaxf(v3,0.f); }
            if (HALF_OUT) {
                __half* Ch = (__half*)Cv;
                *(__half2*)&Ch[(size_t)row0*ldc + col]     = __floats2half2_rn(v0, v1);
                *(__half2*)&Ch[(size_t)(row0+8)*ldc + col] = __floats2half2_rn(v2, v3);
            } else {
                float* Cf = (float*)Cv;
                float2 p0; p0.x = v0; p0.y = v1;
                float2 p1; p1.x = v2; p1.y = v3;
                *(float2*)&Cf[(size_t)row0*ldc + col] = p0;
                *(float2*)&Cf[(size_t)(row0+8)*ldc + col] = p1;
            }
        }
    }
}

// ---------------------------------------------------------------------------
// Flash attention (causal, fp32 math, half I/O). Grid (T/64, H, B), 128 thr.
// 2 threads per query row (HS split 32+32); pair-shfl combines scores.
// qkv half [NTOK][3072]: q at h*64, k at 1024+h*64, v at 2048+h*64.
// ---------------------------------------------------------------------------
__global__ __launch_bounds__(128)
void attn_kernel(const __half* __restrict__ qkv, __half* __restrict__ outp) {
    int qb = blockIdx.x, h = blockIdx.y, b = blockIdx.z;
    int tid = threadIdx.x;
    int ql = tid >> 1, half_ = tid & 1;
    int qi = qb * 64 + ql;
    int hc = half_ * 32;

    const __half* qrow = qkv + ((size_t)(b*TT + qi))*NQKV + h*HS + hc;
    float qr[32];
    #pragma unroll
    for (int e = 0; e < 32; e += 8)
        h8_to_f(*(const uint4*)(qrow + e), qr + e);

    float o[32];
    #pragma unroll
    for (int e = 0; e < 32; e++) o[e] = 0.f;
    float m = -1e30f, l = 0.f;

    __shared__ float Ks[64][68];
    __shared__ float Vs[64][68];

    int kend = qb*64 + 64;
    for (int ks = 0; ks < kend; ks += 64) {
        {
            int jr = tid >> 1;
            int c0 = (tid & 1) * 32;
            const __half* kp = qkv + ((size_t)(b*TT + ks + jr))*NQKV + 1024 + h*HS + c0;
            const __half* vp = qkv + ((size_t)(b*TT + ks + jr))*NQKV + 2048 + h*HS + c0;
            float tmp[8];
            #pragma unroll
            for (int c = 0; c < 32; c += 8) {
                h8_to_f(*(const uint4*)(kp + c), tmp);
                #pragma unroll
                for (int u = 0; u < 8; u++) Ks[jr][c0+c+u] = tmp[u];
                h8_to_f(*(const uint4*)(vp + c), tmp);
                #pragma unroll
                for (int u = 0; u < 8; u++) Vs[jr][c0+c+u] = tmp[u];
            }
        }
        __syncthreads();

        #pragma unroll
        for (int jc = 0; jc < 64; jc += 16) {
            if (ks + jc <= qi) {
                unsigned amask = __activemask();
                float s[16];
                float tmax = -1e30f;
                #pragma unroll
                for (int j = 0; j < 16; j++) {
                    float part = 0.f;
                    #pragma unroll
                    for (int e = 0; e < 32; e++) part = fmaf(qr[e], Ks[jc+j][hc+e], part);
                    float full = (part + __shfl_xor_sync(amask, part, 1)) * ATT_SCALE;
                    if (ks + jc + j > qi) full = -1e30f;
                    s[j] = full;
                    tmax = fmaxf(tmax, full);
                }
                float mnew = fmaxf(m, tmax);
                float corr = __expf(m - mnew);
                l *= corr;
                #pragma unroll
                for (int e = 0; e < 32; e++) o[e] *= corr;
                #pragma unroll
                for (int j = 0; j < 16; j++) {
                    float p = __expf(s[j] - mnew);
                    l += p;
                    #pragma unroll
                    for (int e = 0; e < 32; e++) o[e] = fmaf(p, Vs[jc+j][hc+e], o[e]);
                }
                m = mnew;
            }
        }
        __syncthreads();
    }

    float inv = 1.f / l;
    __half* op = outp + ((size_t)(b*TT + qi))*DD + h*HS + hc;
    #pragma unroll
    for (int e = 0; e < 32; e += 2)
        *(__half2*)(op + e) = __floats2half2_rn(o[e]*inv, o[e+1]*inv);
}

// ---------------------------------------------------------------------------
// Loss
// ---------------------------------------------------------------------------
__global__ void rowloss_kernel(const float* __restrict__ logits,
                               const int* __restrict__ tgt,
                               float* __restrict__ rl) {
    int row = blockIdx.x, tx = threadIdx.x;
    const float* lr = logits + (size_t)row * VV;
    __shared__ float sh[8];
    float mx = -1e30f;
    for (int i = tx; i < VV; i += 256) mx = fmaxf(mx, lr[i]);
    #pragma unroll
    for (int o = 16; o > 0; o >>= 1) mx = fmaxf(mx, __shfl_down_sync(0xffffffffu, mx, o));
    if ((tx & 31) == 0) sh[tx>>5] = mx;
    __syncthreads();
    if (tx == 0) {
        float a = sh[0];
        #pragma unroll
        for (int i = 1; i < 8; i++) a = fmaxf(a, sh[i]);
        sh[0] = a;
    }
    __syncthreads();
    mx = sh[0];
    __syncthreads();
    float se = 0.f;
    for (int i = tx; i < VV; i += 256) se += __expf(lr[i] - mx);
    #pragma unroll
    for (int o = 16; o > 0; o >>= 1) se += __shfl_down_sync(0xffffffffu, se, o);
    if ((tx & 31) == 0) sh[tx>>5] = se;
    __syncthreads();
    if (tx == 0) {
        float s = sh[0];
        #pragma unroll
        for (int i = 1; i < 8; i++) s += sh[i];
        rl[row] = -(lr[tgt[row]] - mx - logf(s));
    }
}

__global__ void finloss_kernel(const float* __restrict__ rl, float* __restrict__ out) {
    int tx = threadIdx.x;
    __shared__ float sh[8];
    float s = 0.f;
    for (int i = tx; i < NTOK; i += 256) s += rl[i];
    #pragma unroll
    for (int o = 16; o > 0; o >>= 1) s += __shfl_down_sync(0xffffffffu, s, o);
    if ((tx & 31) == 0) sh[tx>>5] = s;
    __syncthreads();
    if (tx == 0) {
        float a = 0.f;
        #pragma unroll
        for (int i = 0; i < 8; i++) a += sh[i];
        *out = a * (1.f / NTOK);
    }
}

// ---------------------------------------------------------------------------
// Host orchestration
// ---------------------------------------------------------------------------
extern "C" void kernel_launch(void* const* d_in, const int* in_sizes, int n_in,
                              void* d_out, int out_size) {
    const float* tok_emb = (const float*)d_in[0];
    const float* pos_emb = (const float*)d_in[1];
    const float* ln1_g   = (const float*)d_in[2];
    const float* ln1_b   = (const float*)d_in[3];
    const float* Wq      = (const float*)d_in[4];
    const float* Wk      = (const float*)d_in[5];
    const float* Wv      = (const float*)d_in[6];
    const float* Wo      = (const float*)d_in[7];
    const float* bo      = (const float*)d_in[8];
    const float* ln2_g   = (const float*)d_in[9];
    const float* ln2_b   = (const float*)d_in[10];
    const float* W1      = (const float*)d_in[11];
    const float* b1      = (const float*)d_in[12];
    const float* W2      = (const float*)d_in[13];
    const float* b2      = (const float*)d_in[14];
    const float* lnf_g   = (const float*)d_in[15];
    const float* lnf_b   = (const float*)d_in[16];
    const float* lm_W    = (const float*)d_in[17];
    const float* lm_b    = (const float*)d_in[18];
    const int*   ctx     = (const int*)d_in[19];
    const int*   tgt     = (const int*)d_in[20];

    float *px, *prl, *plfb;
    __half *ph, *pqkv, *patt, *pffn, *pwr;
    cudaGetSymbolAddress((void**)&px,   g_x);
    cudaGetSymbolAddress((void**)&ph,   g_h);
    cudaGetSymbolAddress((void**)&pqkv, g_qkv);
    cudaGetSymbolAddress((void**)&patt, g_att);
    cudaGetSymbolAddress((void**)&pffn, g_ffn);
    cudaGetSymbolAddress((void**)&prl,  g_rowloss);
    cudaGetSymbolAddress((void**)&pwr,  g_wr);
    cudaGetSymbolAddress((void**)&plfb, g_logits_fb);

    cudaFuncSetAttribute(gemm_h<false,false,true >, cudaFuncAttributeMaxDynamicSharedMemorySize, GEMM_SMEM);
    cudaFuncSetAttribute(gemm_h<false,true ,false>, cudaFuncAttributeMaxDynamicSharedMemorySize, GEMM_SMEM);
    cudaFuncSetAttribute(gemm_h<true ,false,true >, cudaFuncAttributeMaxDynamicSharedMemorySize, GEMM_SMEM);
    cudaFuncSetAttribute(gemm_h<false,false,false>, cudaFuncAttributeMaxDynamicSharedMemorySize, GEMM_SMEM);

    const long long LOGITS_N = (long long)NTOK * VV;
    float* logits = ((long long)out_size >= LOGITS_N) ? (float*)d_out : plfb;
    float* lossp = nullptr;
    if ((long long)out_size == LOGITS_N + 1) lossp = (float*)d_out + (size_t)LOGITS_N;
    else if (out_size > 0 && (long long)out_size < LOGITS_N) lossp = (float*)d_out;

    // Prep: one transpose+convert launch, then embedding
    {
        dim3 tb(32, 8);
        transpose_all<<<NT_ALL, tb>>>(Wq, Wk, Wv, Wo, W1, W2, lm_W, pwr);
    }
    embed_kernel<<<(NTOK*DD/4)/256, 256>>>(tok_emb, pos_emb, ctx, px);

    dim3 gQKV(NQKV/BN, NTOK/BM);   // (12, 32)
    dim3 gD(DD/BN,  NTOK/BM);      // (4, 32)
    dim3 gF(FFD/BN, NTOK/BM);      // (16, 32)
    dim3 gV(VV/BN,  NTOK/BM);      // (125, 32)
    dim3 gA(TT/64, HH, BB);        // (16, 16, 4)

    for (int l = 0; l < LL; l++) {
        const __half* wqkv = pwr + OFF_QKV + (size_t)l*NQKV*DD;
        const __half* wo   = pwr + OFF_O   + (size_t)l*DD*DD;
        const __half* w1   = pwr + OFF_W1  + (size_t)l*DD*FFD;
        const __half* w2   = pwr + OFF_W2  + (size_t)l*FFD*DD;

        layernorm_kernel<<<NTOK, 256>>>(px, ln1_g + l*DD, ln1_b + l*DD, ph);
        // fused qkv = h @ Wqkv^T   [4096, 3072] (half out)
        gemm_h<false,false,true><<<gQKV, GEMM_THREADS, GEMM_SMEM>>>(ph, wqkv, nullptr, nullptr, pqkv, NTOK, NQKV, DD, NQKV);
        attn_kernel<<<gA, 128>>>(pqkv, patt);
        // x = x + att @ Wo + bo   (float out, residual)
        gemm_h<false,true,false><<<gD, GEMM_THREADS, GEMM_SMEM>>>(patt, wo, bo + l*DD, px, px, NTOK, DD, DD, DD);
        layernorm_kernel<<<NTOK, 256>>>(px, ln2_g + l*DD, ln2_b + l*DD, ph);
        // ffn = relu(h @ W1 + b1)  (half out)
        gemm_h<true,false,true><<<gF, GEMM_THREADS, GEMM_SMEM>>>(ph, w1, b1 + l*FFD, nullptr, pffn, NTOK, FFD, DD, FFD);
        // x = x + ffn @ W2 + b2   (float out, residual)
        gemm_h<false,true,false><<<gD, GEMM_THREADS, GEMM_SMEM>>>(pffn, w2, b2 + l*DD, px, px, NTOK, DD, FFD, DD);
    }

    layernorm_kernel<<<NTOK, 256>>>(px, lnf_g, lnf_b, ph);
    gemm_h<false,false,false><<<gV, GEMM_THREADS, GEMM_SMEM>>>(ph, pwr + OFF_LM, lm_b, nullptr, logits, NTOK, VV, DD, VV);

    if (lossp) {
        rowloss_kernel<<<NTOK, 256>>>(logits, tgt, prl);
        finloss_kernel<<<1, 256>>>(prl, lossp);
    }
}

// round 11
// speedup vs baseline: 1.0278x; 1.0278x over previous
#include <cuda_runtime.h>
#include <cuda_fp16.h>
#include <math.h>
#include <stdint.h>

// Model constants
#define BB 4
#define TT 1024
#define DD 1024
#define HH 16
#define HS 64
#define LL 8
#define FFD 4096
#define VV 32000
#define NTOK (BB*TT)          // 4096
#define NQKV 3072
#define ATT_SCALE 0.03125f    // D^-0.5 = 1/32

// fp16 GEMM tile config: 128x128x32, 256 threads, 3-stage, 2 CTAs/SM
#define BM 128
#define BN 128
#define BK 32                 // halfs per k-slab
#define STG 3
#define A_STRIDE 40           // halfs per smem row (pad 32->40)
#define B_STRIDE 40
#define A_SLAB_B (BM*A_STRIDE*2)     // 10240 B
#define B_SLAB_B (BN*B_STRIDE*2)     // 10240 B
#define SLAB_B (A_SLAB_B + B_SLAB_B) // 20480 B
#define GEMM_SMEM (STG*SLAB_B)       // 61440 B
#define GEMM_THREADS 256

// Weight scratch offsets (transposed [N][K] half copies)
#define SQ  (LL*HH*DD*HS)        // 8388608
#define SO  (LL*DD*DD)           // 8388608
#define S1  (LL*DD*FFD)          // 33554432
#define SLM (DD*VV)              // 32768000
#define OFF_QKV 0                // [L][3072][1024]
#define OFF_O  (3*SQ)            // [L][1024][1024]
#define OFF_W1 (3*SQ + SO)       // [L][4096][1024]
#define OFF_W2 (3*SQ + SO + S1)  // [L][1024][4096]
#define OFF_LM (3*SQ + SO + 2*S1)// [32000][1024]
#define WTOT   (3*SQ + SO + 2*S1 + SLM)

// transpose tile counts
#define NT_QKV (3*LL*HH*64)      // 24576
#define NT_WO  (LL*32*32)        // 8192
#define NT_W1  (LL*32*128)       // 32768
#define NT_W2  (LL*128*32)       // 32768
#define NT_LM  (32*1000)         // 32000
#define NT_ALL (NT_QKV+NT_WO+NT_W1+NT_W2+NT_LM)  // 130304

// ---------------------------------------------------------------------------
// Scratch (device globals)
// ---------------------------------------------------------------------------
__device__ float  g_x  [(size_t)NTOK*DD];
__device__ __half g_h  [(size_t)NTOK*DD];
__device__ __half g_qkv[(size_t)NTOK*NQKV];
__device__ __half g_att[(size_t)NTOK*DD];
__device__ __half g_ffn[(size_t)NTOK*FFD];
__device__ float  g_rowloss[NTOK];
__device__ __half g_wr [(size_t)WTOT];
__device__ float  g_logits_fb[(size_t)NTOK*VV];

// ---------------------------------------------------------------------------
// Helpers
// ---------------------------------------------------------------------------
__device__ __forceinline__ uint32_t s2u(const void* p) {
    return (uint32_t)__cvta_generic_to_shared(p);
}
__device__ __forceinline__ void cpasync16s(uint32_t saddr, const void* g) {
    asm volatile("cp.async.cg.shared.global [%0], [%1], 16;\n" :: "r"(saddr), "l"(g));
}
__device__ __forceinline__ void cp_commit() { asm volatile("cp.async.commit_group;\n"); }

__device__ __forceinline__ void mma_f16(float c[4], const unsigned a[4], const unsigned b[2]) {
    asm volatile(
        "mma.sync.aligned.m16n8k16.row.col.f32.f16.f16.f32 "
        "{%0,%1,%2,%3}, {%4,%5,%6,%7}, {%8,%9}, {%0,%1,%2,%3};\n"
        : "+f"(c[0]), "+f"(c[1]), "+f"(c[2]), "+f"(c[3])
        : "r"(a[0]), "r"(a[1]), "r"(a[2]), "r"(a[3]), "r"(b[0]), "r"(b[1]));
}

#define LDSM4(r, a) \
    asm volatile("ldmatrix.sync.aligned.m8n8.x4.shared.b16 {%0,%1,%2,%3}, [%4];" \
        : "=r"((r)[0]), "=r"((r)[1]), "=r"((r)[2]), "=r"((r)[3]) : "r"(a))

__device__ __forceinline__ void h8_to_f(uint4 u, float* f) {
    float2 t;
    t = __half22float2(*(const __half2*)&u.x); f[0]=t.x; f[1]=t.y;
    t = __half22float2(*(const __half2*)&u.y); f[2]=t.x; f[3]=t.y;
    t = __half22float2(*(const __half2*)&u.z); f[4]=t.x; f[5]=t.y;
    t = __half22float2(*(const __half2*)&u.w); f[6]=t.x; f[7]=t.y;
}

// ---------------------------------------------------------------------------
// Mega transpose: all weights fp32 [K][N] -> half [N][K] in g_wr, one launch
// ---------------------------------------------------------------------------
__global__ void transpose_all(const float* __restrict__ Wq, const float* __restrict__ Wk,
                              const float* __restrict__ Wv, const float* __restrict__ Wo,
                              const float* __restrict__ W1, const float* __restrict__ W2,
                              const float* __restrict__ lmW, __half* __restrict__ dst) {
    __shared__ float t[32][33];
    int id = blockIdx.x;
    const float* s; __half* d; int sN, dK, kt, nt;

    if (id < NT_QKV) {
        int sel = id / (NT_QKV/3);            // 0=q,1=k,2=v
        int rem = id % (NT_QKV/3);            // 8192
        int mat = rem >> 6;                    // l*16+h
        int tile = rem & 63;
        kt = tile >> 1; nt = tile & 1;
        int l = mat >> 4, h = mat & 15;
        const float* W = sel == 0 ? Wq : (sel == 1 ? Wk : Wv);
        s = W + (size_t)mat * DD * HS;        // [1024][64]
        sN = HS; dK = DD;
        d = dst + OFF_QKV + ((size_t)l*NQKV + sel*DD + h*HS) * DD;
    } else if (id < NT_QKV + NT_WO) {
        int rem = id - NT_QKV;
        int l = rem >> 10; int tile = rem & 1023;
        kt = tile >> 5; nt = tile & 31;
        s = Wo + (size_t)l * DD * DD; sN = DD; dK = DD;
        d = dst + OFF_O + (size_t)l * DD * DD;
    } else if (id < NT_QKV + NT_WO + NT_W1) {
        int rem = id - NT_QKV - NT_WO;
        int l = rem >> 12; int tile = rem & 4095;
        kt = tile >> 7; nt = tile & 127;       // K=1024 (32 kt), N=4096 (128 nt)
        s = W1 + (size_t)l * DD * FFD; sN = FFD; dK = DD;
        d = dst + OFF_W1 + (size_t)l * DD * FFD;
    } else if (id < NT_QKV + NT_WO + NT_W1 + NT_W2) {
        int rem = id - NT_QKV - NT_WO - NT_W1;
        int l = rem >> 12; int tile = rem & 4095;
        kt = tile & 127; nt = tile >> 7;       // K=4096 (128 kt), N=1024 (32 nt)
        s = W2 + (size_t)l * FFD * DD; sN = DD; dK = FFD;
        d = dst + OFF_W2 + (size_t)l * FFD * DD;
    } else {
        int rem = id - NT_QKV - NT_WO - NT_W1 - NT_W2;
        kt = rem % 32; nt = rem / 32;          // K=1024 (32 kt), N=32000 (1000 nt)
        s = lmW; sN = VV; dK = DD;
        d = dst + OFF_LM;
    }

    int tx = threadIdx.x, ty = threadIdx.y;
    #pragma unroll
    for (int i = 0; i < 4; i++) {
        int r = kt*32 + ty + i*8;
        t[ty + i*8][tx] = s[(size_t)r * sN + nt*32 + tx];
    }
    __syncthreads();
    #pragma unroll
    for (int i = 0; i < 4; i++) {
        int n = nt*32 + ty + i*8;
        d[(size_t)n * dK + kt*32 + tx] = __float2half_rn(t[tx][ty + i*8]);
    }
}

// ---------------------------------------------------------------------------
// Embedding (fp32 residual stream)
// ---------------------------------------------------------------------------
__global__ void embed_kernel(const float* __restrict__ tok,
                             const float* __restrict__ pos,
                             const int*   __restrict__ ctx,
                             float* __restrict__ x) {
    int idx = blockIdx.x * blockDim.x + threadIdx.x;
    int col4 = idx & (DD/4 - 1);
    int row  = idx >> 8;
    int t = row & (TT - 1);
    int token = ctx[row];
    float4 a = ((const float4*)(tok + (size_t)token*DD))[col4];
    float4 p = ((const float4*)(pos + (size_t)t*DD))[col4];
    float4 o; o.x=a.x+p.x; o.y=a.y+p.y; o.z=a.z+p.z; o.w=a.w+p.w;
    ((float4*)(x + (size_t)row*DD))[col4] = o;
}

// ---------------------------------------------------------------------------
// LayerNorm: fp32 in, half out (feeds GEMM A)
// ---------------------------------------------------------------------------
__global__ void layernorm_kernel(const float* __restrict__ x,
                                 const float* __restrict__ g,
                                 const float* __restrict__ bta,
                                 __half* __restrict__ out) {
    int row = blockIdx.x, tx = threadIdx.x;
    float4 v = ((const float4*)(x + (size_t)row*DD))[tx];
    float s  = v.x + v.y + v.z + v.w;
    float ss = v.x*v.x + v.y*v.y + v.z*v.z + v.w*v.w;
    __shared__ float sh[16];
    #pragma unroll
    for (int o = 16; o > 0; o >>= 1) {
        s  += __shfl_down_sync(0xffffffffu, s,  o);
        ss += __shfl_down_sync(0xffffffffu, ss, o);
    }
    if ((tx & 31) == 0) { sh[tx>>5] = s; sh[8 + (tx>>5)] = ss; }
    __syncthreads();
    if (tx == 0) {
        float a = 0.f, b2 = 0.f;
        #pragma unroll
        for (int i = 0; i < 8; i++) { a += sh[i]; b2 += sh[8+i]; }
        sh[0] = a; sh[8] = b2;
    }
    __syncthreads();
    float mean = sh[0] * (1.f/DD);
    float var  = sh[8] * (1.f/DD) - mean*mean;
    float r = rsqrtf(var + 1e-5f);
    float4 gg = ((const float4*)g)[tx];
    float4 bb = ((const float4*)bta)[tx];
    __half2 h0 = __floats2half2_rn((v.x-mean)*r*gg.x + bb.x, (v.y-mean)*r*gg.y + bb.y);
    __half2 h1 = __floats2half2_rn((v.z-mean)*r*gg.z + bb.z, (v.w-mean)*r*gg.w + bb.w);
    __half2* op = (__half2*)(out + (size_t)row*DD);
    op[tx*2]   = h0;
    op[tx*2+1] = h1;
}

// ---------------------------------------------------------------------------
// fp16 tensor-core GEMM: C[M,N] = epi(A[M,K] @ Bt[N,K]^T + bias [+Res])
// A row-major [M][K] half, Bt row-major [N][K] half.
// Tile 128x128x32, 256 threads, 8 warps (4Mx2N), 3-stage cp.async,
// single-barrier pipeline, ldmatrix.x4 fragment loads, 2 CTAs/SM.
// ---------------------------------------------------------------------------
template<bool RELU, bool RES, bool HALF_OUT>
__global__ __launch_bounds__(GEMM_THREADS, 2)
void gemm_h(const __half* __restrict__ A, const __half* __restrict__ Bt,
            const float* __restrict__ bias, const float* __restrict__ Res,
            void* __restrict__ Cv, int M, int N, int K, int ldc) {
    extern __shared__ char sm[];

    int tx = threadIdx.x;
    int lane = tx & 31, w = tx >> 5;
    int gid = lane >> 2, tig = lane & 3;
    int warpM = w & 3;   // 0..3 -> 32-row strip
    int warpN = w >> 2;  // 0..1 -> 64-col strip
    int bm = blockIdx.y * BM;
    int bn = blockIdx.x * BN;

    float acc[2][8][4];
    #pragma unroll
    for (int mt = 0; mt < 2; mt++)
        #pragma unroll
        for (int nt = 0; nt < 8; nt++)
            #pragma unroll
            for (int i = 0; i < 4; i++) acc[mt][nt][i] = 0.f;

    uint32_t sb = s2u(sm);

    // ldmatrix per-thread offsets (halfs, within slab)
    int lane15 = lane & 15;
    int lhi8 = (lane >> 4) * 8;
    int offA0 = (warpM*32 + lane15) * A_STRIDE + lhi8;          // mt=0
    int offA1 = offA0 + 16 * A_STRIDE;                          // mt=1
    int offB0 = (warpN*64 + lane15) * B_STRIDE + lhi8;          // ntPair 0

    auto load_slab = [&](int st, int k0) {
        uint32_t ab = sb + st * SLAB_B;
        uint32_t bb = ab + A_SLAB_B;
        // A: 128 rows x 4 chunks = 512 chunks / 256 thr = 2 each
        #pragma unroll
        for (int i = 0; i < 2; i++) {
            int id = tx + i * GEMM_THREADS;
            int r = id >> 2;
            int c = id & 3;
            cpasync16s(ab + r * (A_STRIDE*2) + c * 16,
                       A + (size_t)(bm + r) * K + k0 + c * 8);
        }
        // B: same shape
        #pragma unroll
        for (int i = 0; i < 2; i++) {
            int id = tx + i * GEMM_THREADS;
            int n = id >> 2;
            int c = id & 3;
            cpasync16s(bb + n * (B_STRIDE*2) + c * 16,
                       Bt + (size_t)(bn + n) * K + k0 + c * 8);
        }
    };

    int S = K / BK;
    load_slab(0, 0);    cp_commit();
    load_slab(1, BK);   cp_commit();

    for (int s = 0; s < S; s++) {
        int b = s % STG;
        if (s == S - 1) asm volatile("cp.async.wait_group 0;\n");
        else            asm volatile("cp.async.wait_group 1;\n");
        __syncthreads();

        if (s + 2 < S) {
            load_slab((s + 2) % STG, (s + 2) * BK);
            cp_commit();
        }

        uint32_t abase = sb + b * SLAB_B;
        uint32_t bbase = abase + A_SLAB_B;
        #pragma unroll
        for (int kk = 0; kk < BK; kk += 16) {
            unsigned a0[4], a1[4], bq[4][4];
            LDSM4(a0, abase + (offA0 + kk) * 2);
            LDSM4(a1, abase + (offA1 + kk) * 2);
            #pragma unroll
            for (int p = 0; p < 4; p++)
                LDSM4(bq[p], bbase + (offB0 + p * 16 * B_STRIDE + kk) * 2);
            #pragma unroll
            for (int p = 0; p < 4; p++) {
                unsigned ble[2] = { bq[p][0], bq[p][2] };   // nt = 2p
                unsigned bro[2] = { bq[p][1], bq[p][3] };   // nt = 2p+1
                mma_f16(acc[0][2*p],   a0, ble);
                mma_f16(acc[1][2*p],   a1, ble);
                mma_f16(acc[0][2*p+1], a0, bro);
                mma_f16(acc[1][2*p+1], a1, bro);
            }
        }
    }

    // Epilogue: direct register->gmem
    #pragma unroll
    for (int mt = 0; mt < 2; mt++) {
        int row0 = bm + warpM * 32 + mt * 16 + gid;
        #pragma unroll
        for (int nt = 0; nt < 8; nt++) {
            int col = bn + warpN * 64 + nt * 8 + tig * 2;
            float b0 = 0.f, b1 = 0.f;
            if (bias) { b0 = bias[col]; b1 = bias[col + 1]; }
            float v0 = acc[mt][nt][0] + b0;
            float v1 = acc[mt][nt][1] + b1;
            float v2 = acc[mt][nt][2] + b0;
            float v3 = acc[mt][nt][3] + b1;
            if (RES) {
                v0 += Res[(size_t)row0*ldc + col];
                v1 += Res[(size_t)row0*ldc + col + 1];
                v2 += Res[(size_t)(row0+8)*ldc + col];
                v3 += Res[(size_t)(row0+8)*ldc + col + 1];
            }
            if (RELU) { v0 = fmaxf(v0,0.f); v1 = fmaxf(v1,0.f); v2 = fmaxf(v2,0.f); v3 = fmaxf(v3,0.f); }
            if (HALF_OUT) {
                __half* Ch = (__half*)Cv;
                *(__half2*)&Ch[(size_t)row0*ldc + col]     = __floats2half2_rn(v0, v1);
                *(__half2*)&Ch[(size_t)(row0+8)*ldc + col] = __floats2half2_rn(v2, v3);
            } else {
                float* Cf = (float*)Cv;
                float2 p0; p0.x = v0; p0.y = v1;
                float2 p1; p1.x = v2; p1.y = v3;
                *(float2*)&Cf[(size_t)row0*ldc + col] = p0;
                *(float2*)&Cf[(size_t)(row0+8)*ldc + col] = p1;
            }
        }
    }
}

// ---------------------------------------------------------------------------
// Flash attention (causal, fp32 math, half I/O). Grid (T/64, H, B), 128 thr.
// 2 threads per query row (HS split 32+32); pair-shfl combines scores.
// qkv half [NTOK][3072]: q at h*64, k at 1024+h*64, v at 2048+h*64.
// ---------------------------------------------------------------------------
__global__ __launch_bounds__(128)
void attn_kernel(const __half* __restrict__ qkv, __half* __restrict__ outp) {
    int qb = blockIdx.x, h = blockIdx.y, b = blockIdx.z;
    int tid = threadIdx.x;
    int ql = tid >> 1, half_ = tid & 1;
    int qi = qb * 64 + ql;
    int hc = half_ * 32;

    const __half* qrow = qkv + ((size_t)(b*TT + qi))*NQKV + h*HS + hc;
    float qr[32];
    #pragma unroll
    for (int e = 0; e < 32; e += 8)
        h8_to_f(*(const uint4*)(qrow + e), qr + e);

    float o[32];
    #pragma unroll
    for (int e = 0; e < 32; e++) o[e] = 0.f;
    float m = -1e30f, l = 0.f;

    __shared__ float Ks[64][68];
    __shared__ float Vs[64][68];

    int kend = qb*64 + 64;
    for (int ks = 0; ks < kend; ks += 64) {
        {
            int jr = tid >> 1;
            int c0 = (tid & 1) * 32;
            const __half* kp = qkv + ((size_t)(b*TT + ks + jr))*NQKV + 1024 + h*HS + c0;
            const __half* vp = qkv + ((size_t)(b*TT + ks + jr))*NQKV + 2048 + h*HS + c0;
            float tmp[8];
            #pragma unroll
            for (int c = 0; c < 32; c += 8) {
                h8_to_f(*(const uint4*)(kp + c), tmp);
                #pragma unroll
                for (int u = 0; u < 8; u++) Ks[jr][c0+c+u] = tmp[u];
                h8_to_f(*(const uint4*)(vp + c), tmp);
                #pragma unroll
                for (int u = 0; u < 8; u++) Vs[jr][c0+c+u] = tmp[u];
            }
        }
        __syncthreads();

        #pragma unroll
        for (int jc = 0; jc < 64; jc += 16) {
            if (ks + jc <= qi) {
                unsigned amask = __activemask();
                float s[16];
                float tmax = -1e30f;
                #pragma unroll
                for (int j = 0; j < 16; j++) {
                    float part = 0.f;
                    #pragma unroll
                    for (int e = 0; e < 32; e++) part = fmaf(qr[e], Ks[jc+j][hc+e], part);
                    float full = (part + __shfl_xor_sync(amask, part, 1)) * ATT_SCALE;
                    if (ks + jc + j > qi) full = -1e30f;
                    s[j] = full;
                    tmax = fmaxf(tmax, full);
                }
                float mnew = fmaxf(m, tmax);
                float corr = __expf(m - mnew);
                l *= corr;
                #pragma unroll
                for (int e = 0; e < 32; e++) o[e] *= corr;
                #pragma unroll
                for (int j = 0; j < 16; j++) {
                    float p = __expf(s[j] - mnew);
                    l += p;
                    #pragma unroll
                    for (int e = 0; e < 32; e++) o[e] = fmaf(p, Vs[jc+j][hc+e], o[e]);
                }
                m = mnew;
            }
        }
        __syncthreads();
    }

    float inv = 1.f / l;
    __half* op = outp + ((size_t)(b*TT + qi))*DD + h*HS + hc;
    #pragma unroll
    for (int e = 0; e < 32; e += 2)
        *(__half2*)(op + e) = __floats2half2_rn(o[e]*inv, o[e+1]*inv);
}

// ---------------------------------------------------------------------------
// Loss
// ---------------------------------------------------------------------------
__global__ void rowloss_kernel(const float* __restrict__ logits,
                               const int* __restrict__ tgt,
                               float* __restrict__ rl) {
    int row = blockIdx.x, tx = threadIdx.x;
    const float* lr = logits + (size_t)row * VV;
    __shared__ float sh[8];
    float mx = -1e30f;
    for (int i = tx; i < VV; i += 256) mx = fmaxf(mx, lr[i]);
    #pragma unroll
    for (int o = 16; o > 0; o >>= 1) mx = fmaxf(mx, __shfl_down_sync(0xffffffffu, mx, o));
    if ((tx & 31) == 0) sh[tx>>5] = mx;
    __syncthreads();
    if (tx == 0) {
        float a = sh[0];
        #pragma unroll
        for (int i = 1; i < 8; i++) a = fmaxf(a, sh[i]);
        sh[0] = a;
    }
    __syncthreads();
    mx = sh[0];
    __syncthreads();
    float se = 0.f;
    for (int i = tx; i < VV; i += 256) se += __expf(lr[i] - mx);
    #pragma unroll
    for (int o = 16; o > 0; o >>= 1) se += __shfl_down_sync(0xffffffffu, se, o);
    if ((tx & 31) == 0) sh[tx>>5] = se;
    __syncthreads();
    if (tx == 0) {
        float s = sh[0];
        #pragma unroll
        for (int i = 1; i < 8; i++) s += sh[i];
        rl[row] = -(lr[tgt[row]] - mx - logf(s));
    }
}

__global__ void finloss_kernel(const float* __restrict__ rl, float* __restrict__ out) {
    int tx = threadIdx.x;
    __shared__ float sh[8];
    float s = 0.f;
    for (int i = tx; i < NTOK; i += 256) s += rl[i];
    #pragma unroll
    for (int o = 16; o > 0; o >>= 1) s += __shfl_down_sync(0xffffffffu, s, o);
    if ((tx & 31) == 0) sh[tx>>5] = s;
    __syncthreads();
    if (tx == 0) {
        float a = 0.f;
        #pragma unroll
        for (int i = 0; i < 8; i++) a += sh[i];
        *out = a * (1.f / NTOK);
    }
}

// ---------------------------------------------------------------------------
// Host orchestration
// ---------------------------------------------------------------------------
extern "C" void kernel_launch(void* const* d_in, const int* in_sizes, int n_in,
                              void* d_out, int out_size) {
    const float* tok_emb = (const float*)d_in[0];
    const float* pos_emb = (const float*)d_in[1];
    const float* ln1_g   = (const float*)d_in[2];
    const float* ln1_b   = (const float*)d_in[3];
    const float* Wq      = (const float*)d_in[4];
    const float* Wk      = (const float*)d_in[5];
    const float* Wv      = (const float*)d_in[6];
    const float* Wo      = (const float*)d_in[7];
    const float* bo      = (const float*)d_in[8];
    const float* ln2_g   = (const float*)d_in[9];
    const float* ln2_b   = (const float*)d_in[10];
    const float* W1      = (const float*)d_in[11];
    const float* b1      = (const float*)d_in[12];
    const float* W2      = (const float*)d_in[13];
    const float* b2      = (const float*)d_in[14];
    const float* lnf_g   = (const float*)d_in[15];
    const float* lnf_b   = (const float*)d_in[16];
    const float* lm_W    = (const float*)d_in[17];
    const float* lm_b    = (const float*)d_in[18];
    const int*   ctx     = (const int*)d_in[19];
    const int*   tgt     = (const int*)d_in[20];

    float *px, *prl, *plfb;
    __half *ph, *pqkv, *patt, *pffn, *pwr;
    cudaGetSymbolAddress((void**)&px,   g_x);
    cudaGetSymbolAddress((void**)&ph,   g_h);
    cudaGetSymbolAddress((void**)&pqkv, g_qkv);
    cudaGetSymbolAddress((void**)&patt, g_att);
    cudaGetSymbolAddress((void**)&pffn, g_ffn);
    cudaGetSymbolAddress((void**)&prl,  g_rowloss);
    cudaGetSymbolAddress((void**)&pwr,  g_wr);
    cudaGetSymbolAddress((void**)&plfb, g_logits_fb);

    cudaFuncSetAttribute(gemm_h<false,false,true >, cudaFuncAttributeMaxDynamicSharedMemorySize, GEMM_SMEM);
    cudaFuncSetAttribute(gemm_h<false,true ,false>, cudaFuncAttributeMaxDynamicSharedMemorySize, GEMM_SMEM);
    cudaFuncSetAttribute(gemm_h<true ,false,true >, cudaFuncAttributeMaxDynamicSharedMemorySize, GEMM_SMEM);
    cudaFuncSetAttribute(gemm_h<false,false,false>, cudaFuncAttributeMaxDynamicSharedMemorySize, GEMM_SMEM);

    const long long LOGITS_N = (long long)NTOK * VV;
    float* logits = ((long long)out_size >= LOGITS_N) ? (float*)d_out : plfb;
    float* lossp = nullptr;
    if ((long long)out_size == LOGITS_N + 1) lossp = (float*)d_out + (size_t)LOGITS_N;
    else if (out_size > 0 && (long long)out_size < LOGITS_N) lossp = (float*)d_out;

    // Prep: one transpose+convert launch, then embedding
    {
        dim3 tb(32, 8);
        transpose_all<<<NT_ALL, tb>>>(Wq, Wk, Wv, Wo, W1, W2, lm_W, pwr);
    }
    embed_kernel<<<(NTOK*DD/4)/256, 256>>>(tok_emb, pos_emb, ctx, px);

    dim3 gQKV(NQKV/BN, NTOK/BM);   // (24, 32)
    dim3 gD(DD/BN,  NTOK/BM);      // (8, 32)
    dim3 gF(FFD/BN, NTOK/BM);      // (32, 32)
    dim3 gV(VV/BN,  NTOK/BM);      // (250, 32)
    dim3 gA(TT/64, HH, BB);        // (16, 16, 4)

    for (int l = 0; l < LL; l++) {
        const __half* wqkv = pwr + OFF_QKV + (size_t)l*NQKV*DD;
        const __half* wo   = pwr + OFF_O   + (size_t)l*DD*DD;
        const __half* w1   = pwr + OFF_W1  + (size_t)l*DD*FFD;
        const __half* w2   = pwr + OFF_W2  + (size_t)l*FFD*DD;

        layernorm_kernel<<<NTOK, 256>>>(px, ln1_g + l*DD, ln1_b + l*DD, ph);
        // fused qkv = h @ Wqkv^T   [4096, 3072] (half out)
        gemm_h<false,false,true><<<gQKV, GEMM_THREADS, GEMM_SMEM>>>(ph, wqkv, nullptr, nullptr, pqkv, NTOK, NQKV, DD, NQKV);
        attn_kernel<<<gA, 128>>>(pqkv, patt);
        // x = x + att @ Wo + bo   (float out, residual)
        gemm_h<false,true,false><<<gD, GEMM_THREADS, GEMM_SMEM>>>(patt, wo, bo + l*DD, px, px, NTOK, DD, DD, DD);
        layernorm_kernel<<<NTOK, 256>>>(px, ln2_g + l*DD, ln2_b + l*DD, ph);
        // ffn = relu(h @ W1 + b1)  (half out)
        gemm_h<true,false,true><<<gF, GEMM_THREADS, GEMM_SMEM>>>(ph, w1, b1 + l*FFD, nullptr, pffn, NTOK, FFD, DD, FFD);
        // x = x + ffn @ W2 + b2   (float out, residual)
        gemm_h<false,true,false><<<gD, GEMM_THREADS, GEMM_SMEM>>>(pffn, w2, b2 + l*DD, px, px, NTOK, DD, FFD, DD);
    }

    layernorm_kernel<<<NTOK, 256>>>(px, lnf_g, lnf_b, ph);
    gemm_h<false,false,false><<<gV, GEMM_THREADS, GEMM_SMEM>>>(ph, pwr + OFF_LM, lm_b, nullptr, logits, NTOK, VV, DD, VV);

    if (lossp) {
        rowloss_kernel<<<NTOK, 256>>>(logits, tgt, prl);
        finloss_kernel<<<1, 256>>>(prl, lossp);
    }
}